// round 11
// baseline (speedup 1.0000x reference)
#include <cuda_runtime.h>
#include <cuda_fp16.h>
#include <math.h>

#define Nn 100000
#define Ee 1600000
#define ETOT (Ee + Nn)
#define Hh 64
#define Gg 512
#define CAP 96    // smem-cached (src, ex) per dst; deg>CAP uses recompute fallback
#define NB 98     // ceil(Nn/1024) scan blocks

// ---------------- device scratch (no allocation allowed) ----------------
__device__ __align__(256) __half g_hh[(size_t)Nn * Hh];  // h = xW (fp16)
__device__ __align__(256) float g_agg[(size_t)Nn * Hh];  // normalized attention output
__device__ float g_ls[Nn];
__device__ float g_ld[Nn];
__device__ float g_pool[Gg * Hh];
__device__ int   g_deg[Nn];
__device__ int   g_rowptr[Nn + 1];
__device__ int   g_cursor[Nn];
__device__ int   g_csrc[ETOT];
__device__ int   g_batch[Nn];
__device__ int   g_bsum[NB], g_boff[NB];
__device__ int   g_ei32, g_b32;   // dtype flags: 1 = int32 packing, 0 = int64

// ============ zero degrees + dtype probe (fused; capture-safe) ============
__global__ void zeroprobe_kernel(const void* ei, const void* batch) {
    if (blockIdx.x < 391) {
        int i = blockIdx.x * 256 + threadIdx.x;
        if (i < Nn) g_deg[i] = 0;
    } else {
        int tid = threadIdx.x;
        if (tid == 0) { g_ei32 = 0; g_b32 = 0; }
        __syncthreads();
        const long long* e64 = (const long long*)ei;   // safe range both interps
        long long v = e64[(tid * 997) % Ee];
        if ((unsigned long long)v >= (unsigned long long)Nn) atomicOr(&g_ei32, 1);
        const long long* b64 = (const long long*)batch;
        long long w = b64[(long long)tid * (Nn / 2 - 1) / 255];
        if ((unsigned long long)w >= (unsigned long long)Gg) atomicOr(&g_b32, 1);
    }
}

__device__ __forceinline__ void load_edge(const void* ei, int i, int& src, int& dst) {
    if (i < Ee) {
        if (g_ei32) {
            const int* p = (const int*)ei;
            src = p[i]; dst = p[Ee + i];
        } else {
            const long long* p = (const long long*)ei;
            src = (int)p[i]; dst = (int)p[Ee + i];
        }
    } else {
        src = dst = i - Ee;   // self loops
    }
}

__global__ void count_kernel(const void* ei) {
    int i = blockIdx.x * 256 + threadIdx.x;
    if (i >= ETOT) return;
    int src, dst;
    load_edge(ei, i, src, dst);
    atomicAdd(&g_deg[dst], 1);
}

// ============ 3-phase multi-block exclusive scan ============
__global__ void scanA_kernel() {
    __shared__ int warp_sums[32];
    int tid = threadIdx.x, lane = tid & 31, wid = tid >> 5;
    int i = blockIdx.x * 1024 + tid;
    int v = (i < Nn) ? g_deg[i] : 0;
    int x = v;
#pragma unroll
    for (int off = 1; off < 32; off <<= 1) {
        int y = __shfl_up_sync(0xffffffffu, x, off);
        if (lane >= off) x += y;
    }
    if (lane == 31) warp_sums[wid] = x;
    __syncthreads();
    if (wid == 0) {
        int w = warp_sums[lane];
#pragma unroll
        for (int off = 1; off < 32; off <<= 1) {
            int y = __shfl_up_sync(0xffffffffu, w, off);
            if (lane >= off) w += y;
        }
        warp_sums[lane] = w;
    }
    __syncthreads();
    int woff = wid ? warp_sums[wid - 1] : 0;
    if (i < Nn) g_rowptr[i] = woff + x - v;
    if (tid == 0) g_bsum[blockIdx.x] = warp_sums[31];
}

__global__ void scanB_kernel() {
    __shared__ int ws[4];
    int tid = threadIdx.x, lane = tid & 31, wid = tid >> 5;
    int v = (tid < NB) ? g_bsum[tid] : 0;
    int x = v;
#pragma unroll
    for (int off = 1; off < 32; off <<= 1) {
        int y = __shfl_up_sync(0xffffffffu, x, off);
        if (lane >= off) x += y;
    }
    if (lane == 31) ws[wid] = x;
    __syncthreads();
    int woff = 0;
    for (int k = 0; k < wid; k++) woff += ws[k];
    if (tid < NB) g_boff[tid] = woff + x - v;
    if (tid == 0) g_rowptr[Nn] = ETOT;
}

__global__ void scanC_kernel(const void* batch) {
    int i = blockIdx.x * 1024 + threadIdx.x;
    if (i >= Nn) return;
    int r = g_rowptr[i] + g_boff[blockIdx.x];
    g_rowptr[i] = r;
    g_cursor[i] = r;
    g_batch[i] = g_b32 ? ((const int*)batch)[i] : (int)((const long long*)batch)[i];
}

__global__ void scatter_kernel(const void* ei) {
    int i = blockIdx.x * 256 + threadIdx.x;
    if (i >= ETOT) return;
    int src, dst;
    load_edge(ei, i, src, dst);
    int pos = atomicAdd(&g_cursor[dst], 1);
    g_csrc[pos] = src;
}

// ======== GEMM: h = X @ W (fp16 out), ls/ld reductions. 16 nodes/block ======
template <int F, bool TRANS>
__global__ void gemm_kernel(const float* __restrict__ xin,
                            const float* __restrict__ W,
                            const float* __restrict__ a_s,
                            const float* __restrict__ a_d,
                            const float* __restrict__ bprev) {
    __shared__ float Ws[F * Hh];
    __shared__ float xs[16][F];
    __shared__ float as_s[Hh], ad_s[Hh], bs[Hh];
    __shared__ float ssum[8][4][2];

    int tid = threadIdx.x;                 // 256 threads
    for (int i = tid; i < F * Hh; i += 256) Ws[i] = W[i];
    if (tid < Hh) {
        as_s[tid] = a_s[tid];
        ad_s[tid] = a_d[tid];
        if (TRANS) bs[tid] = bprev[tid];
    }
    __syncthreads();   // bs/Ws visible before staging reads them

    int n0 = blockIdx.x * 16;
    for (int i = tid; i < 16 * F; i += 256) {
        int node = i / F, col = i % F;
        float v;
        if (TRANS) {
            v = g_agg[(size_t)(n0 + node) * Hh + col] + bs[col];
            v = v > 0.f ? v : (expf(v) - 1.f);   // ELU
        } else {
            v = xin[(n0 + node) * F + col];
        }
        xs[node][col] = v;
    }
    __syncthreads();

    int local = tid >> 6;                  // 0..3 -> node group
    int j     = tid & 63;                  // output column
    float acc[4] = {0.f, 0.f, 0.f, 0.f};
#pragma unroll 16
    for (int k = 0; k < F; k++) {
        float w = Ws[k * Hh + j];
#pragma unroll
        for (int q = 0; q < 4; q++) acc[q] += xs[local * 4 + q][k] * w;
    }
#pragma unroll
    for (int q = 0; q < 4; q++)
        g_hh[(size_t)(n0 + local * 4 + q) * Hh + j] = __float2half(acc[q]);

    float asj = as_s[j], adj = ad_s[j];
    int warp = tid >> 5;
#pragma unroll
    for (int q = 0; q < 4; q++) {
        float rs = acc[q] * asj;
        float rd = acc[q] * adj;
#pragma unroll
        for (int off = 16; off; off >>= 1) {
            rs += __shfl_down_sync(0xffffffffu, rs, off);
            rd += __shfl_down_sync(0xffffffffu, rd, off);
        }
        if ((tid & 31) == 0) { ssum[warp][q][0] = rs; ssum[warp][q][1] = rd; }
    }
    __syncthreads();
    if (j < 4) {   // one thread per (local, q=j)
        int n = n0 + local * 4 + j;
        g_ls[n] = ssum[2 * local][j][0] + ssum[2 * local + 1][j][0];
        g_ld[n] = ssum[2 * local][j][1] + ssum[2 * local + 1][j][1];
    }
}

// == aggregation: warp/dst; smem-cached (src, ex); 4 edges in flight ==
__global__ void agg_kernel() {
    __shared__ float se[8][CAP];
    __shared__ int   ss[8][CAP];
    int gwarp = (blockIdx.x * 256 + threadIdx.x) >> 5;
    int lane  = threadIdx.x & 31;
    int wl    = threadIdx.x >> 5;
    if (gwarp >= Nn) return;
    int dst = gwarp;
    int r0 = g_rowptr[dst], r1 = g_rowptr[dst + 1];
    int d  = r1 - r0;
    float ldv = g_ld[dst];

    // pass 1: load src, compute logits, cache (src, e), running max
    float m = -INFINITY;
    for (int k = lane; k < d; k += 32) {
        int src = g_csrc[r0 + k];
        float e = g_ls[src] + ldv;
        e = e > 0.f ? e : 0.2f * e;
        if (k < CAP) { se[wl][k] = e; ss[wl][k] = src; }
        m = fmaxf(m, e);
    }
#pragma unroll
    for (int off = 16; off; off >>= 1)
        m = fmaxf(m, __shfl_xor_sync(0xffffffffu, m, off));

    // pass 1.5: ex = exp(e - m) in place; den reduction
    float den = 0.f;
    for (int k = lane; k < d; k += 32) {
        float e;
        if (k < CAP) e = se[wl][k];
        else {
            int src = g_csrc[r0 + k];
            e = g_ls[src] + ldv; e = e > 0.f ? e : 0.2f * e;
        }
        float ex = __expf(e - m);
        if (k < CAP) se[wl][k] = ex;
        den += ex;
    }
#pragma unroll
    for (int off = 16; off; off >>= 1)
        den += __shfl_xor_sync(0xffffffffu, den, off);
    __syncwarp();

    // pass 2: 4 subgroups of 8 lanes, one edge each; lane loads 16B (8 halves)
    int sub = lane >> 3;
    int l8  = lane & 7;
    float acc[8] = {0.f, 0.f, 0.f, 0.f, 0.f, 0.f, 0.f, 0.f};
    for (int kk = sub; kk < d; kk += 4) {
        int src; float ex;
        if (kk < CAP) { src = ss[wl][kk]; ex = se[wl][kk]; }
        else {
            src = g_csrc[r0 + kk];
            float e = g_ls[src] + ldv; e = e > 0.f ? e : 0.2f * e;
            ex = __expf(e - m);
        }
        float4 raw = *reinterpret_cast<const float4*>(g_hh + (size_t)src * Hh + l8 * 8);
        const __half2* h2 = reinterpret_cast<const __half2*>(&raw);
#pragma unroll
        for (int t = 0; t < 4; t++) {
            float2 f = __half22float2(h2[t]);
            acc[2 * t]     += ex * f.x;
            acc[2 * t + 1] += ex * f.y;
        }
    }
#pragma unroll
    for (int t = 0; t < 8; t++) {
        acc[t] += __shfl_xor_sync(0xffffffffu, acc[t], 8);
        acc[t] += __shfl_xor_sync(0xffffffffu, acc[t], 16);
    }
    if (sub == 0) {
        float inv = 1.f / den;
        float4 o0 = make_float4(acc[0] * inv, acc[1] * inv, acc[2] * inv, acc[3] * inv);
        float4 o1 = make_float4(acc[4] * inv, acc[5] * inv, acc[6] * inv, acc[7] * inv);
        float4* op = reinterpret_cast<float4*>(g_agg + (size_t)dst * Hh + l8 * 8);
        op[0] = o0; op[1] = o1;
    }
}

// ================= pooling: sorted batch -> contiguous ranges ============
__device__ __forceinline__ int lower_bound_batch(int key) {
    int lo = 0, hi = Nn;
    while (lo < hi) {
        int mid = (lo + hi) >> 1;
        if (g_batch[mid] < key) lo = mid + 1; else hi = mid;
    }
    return lo;
}

__global__ void pool_kernel(const float* __restrict__ b4) {
    __shared__ int s_lo, s_hi;
    __shared__ float red[4][Hh];
    int g = blockIdx.x;
    int tid = threadIdx.x;          // 256 threads
    int j = tid & 63, c = tid >> 6;
    if (tid == 0) s_lo = lower_bound_batch(g);
    if (tid == 1) s_hi = lower_bound_batch(g + 1);
    __syncthreads();
    float bj = b4[j];
    float mx = -INFINITY;
    for (int n = s_lo + c; n < s_hi; n += 4) {
        float v = g_agg[(size_t)n * Hh + j] + bj;
        v = v > 0.f ? v : (expf(v) - 1.f);
        mx = fmaxf(mx, v);
    }
    red[c][j] = mx;
    __syncthreads();
    if (c == 0) {
        mx = fmaxf(fmaxf(red[0][j], red[1][j]), fmaxf(red[2][j], red[3][j]));
        g_pool[g * Hh + j] = mx;
    }
}

// ================= final linear =================
__global__ void final_kernel(const float* __restrict__ lw,
                             const float* __restrict__ lb,
                             float* __restrict__ out) {
    int g = blockIdx.x, j = threadIdx.x;   // 64 threads
    float p = g_pool[g * Hh + j];
    if (!isfinite(p)) p = 0.f;
    float c0 = p * lw[j * 2 + 0];
    float c1 = p * lw[j * 2 + 1];
#pragma unroll
    for (int off = 16; off; off >>= 1) {
        c0 += __shfl_down_sync(0xffffffffu, c0, off);
        c1 += __shfl_down_sync(0xffffffffu, c1, off);
    }
    __shared__ float s[2][2];
    if ((j & 31) == 0) { s[j >> 5][0] = c0; s[j >> 5][1] = c1; }
    __syncthreads();
    if (j == 0) {
        out[2 * g + 0] = s[0][0] + s[1][0] + lb[0];
        out[2 * g + 1] = s[0][1] + s[1][1] + lb[1];
    }
}

// ================= launch =================
extern "C" void kernel_launch(void* const* d_in, const int* in_sizes, int n_in,
                              void* d_out, int out_size) {
    const float* x     = (const float*)d_in[0];
    const void*  ei    = d_in[1];
    const void*  batch = d_in[2];
    const float *W[5], *as[5], *ad[5], *b[5];
    for (int l = 0; l < 5; l++) {
        W[l]  = (const float*)d_in[3 + 4 * l];
        as[l] = (const float*)d_in[4 + 4 * l];
        ad[l] = (const float*)d_in[5 + 4 * l];
        b[l]  = (const float*)d_in[6 + 4 * l];
    }
    const float* lw = (const float*)d_in[23];
    const float* lb = (const float*)d_in[24];
    float* out = (float*)d_out;

    zeroprobe_kernel<<<392, 256>>>(ei, batch);
    count_kernel<<<(ETOT + 255) / 256, 256>>>(ei);
    scanA_kernel<<<NB, 1024>>>();
    scanB_kernel<<<1, 128>>>();
    scanC_kernel<<<NB, 1024>>>(batch);
    scatter_kernel<<<(ETOT + 255) / 256, 256>>>(ei);

    for (int l = 0; l < 5; l++) {
        if (l == 0)
            gemm_kernel<14, false><<<Nn / 16, 256>>>(x, W[0], as[0], ad[0], nullptr);
        else
            gemm_kernel<64, true><<<Nn / 16, 256>>>(nullptr, W[l], as[l], ad[l], b[l - 1]);
        agg_kernel<<<(Nn * 32 + 255) / 256, 256>>>();
    }
    pool_kernel<<<Gg, 256>>>(b[4]);
    final_kernel<<<Gg, 64>>>(lw, lb, out);
}

// round 12
// speedup vs baseline: 1.2068x; 1.2068x over previous
#include <cuda_runtime.h>
#include <cuda_fp16.h>
#include <math.h>

#define Nn 100000
#define Ee 1600000
#define ETOT (Ee + Nn)
#define Hh 64
#define Gg 512
#define CAP 96    // smem-cached (src, ex) per dst; deg>CAP uses recompute fallback
#define NB 98     // ceil(Nn/1024) scan blocks

typedef unsigned long long ull;

// ---------------- device scratch (no allocation allowed) ----------------
__device__ __align__(256) __half g_hh[(size_t)Nn * Hh];  // h = xW (fp16)
__device__ __align__(256) float g_agg[(size_t)Nn * Hh];  // normalized attention output
__device__ float g_ls[Nn];
__device__ float g_ld[Nn];
__device__ float g_pool[Gg * Hh];
__device__ int   g_deg[Nn];
__device__ int   g_rowptr[Nn + 1];
__device__ int   g_cursor[Nn];
__device__ int   g_csrc[ETOT];
__device__ int   g_batch[Nn];
__device__ int   g_bsum[NB], g_boff[NB];
__device__ int   g_ei32, g_b32;   // dtype flags: 1 = int32 packing, 0 = int64

// ---------------- f32x2 packed-FMA helpers (sm_103a) ----------------
__device__ __forceinline__ ull pk2(float x, float y) {
    ull r; asm("mov.b64 %0, {%1, %2};" : "=l"(r) : "f"(x), "f"(y)); return r;
}
__device__ __forceinline__ ull dup2(float x) {
    ull r; asm("mov.b64 %0, {%1, %1};" : "=l"(r) : "f"(x)); return r;
}
__device__ __forceinline__ void ffma2(ull& d, ull a, ull b) {
    asm("fma.rn.f32x2 %0, %1, %2, %0;" : "+l"(d) : "l"(a), "l"(b));
}
__device__ __forceinline__ float2 unpk(ull a) {
    float2 f; asm("mov.b64 {%0, %1}, %2;" : "=f"(f.x), "=f"(f.y) : "l"(a)); return f;
}

// ============ zero degrees + dtype probe (fused; capture-safe) ============
__global__ void zeroprobe_kernel(const void* ei, const void* batch) {
    if (blockIdx.x < 391) {
        int i = blockIdx.x * 256 + threadIdx.x;
        if (i < Nn) g_deg[i] = 0;
    } else {
        int tid = threadIdx.x;
        if (tid == 0) { g_ei32 = 0; g_b32 = 0; }
        __syncthreads();
        const long long* e64 = (const long long*)ei;   // safe range both interps
        long long v = e64[(tid * 997) % Ee];
        if ((unsigned long long)v >= (unsigned long long)Nn) atomicOr(&g_ei32, 1);
        const long long* b64 = (const long long*)batch;
        long long w = b64[(long long)tid * (Nn / 2 - 1) / 255];
        if ((unsigned long long)w >= (unsigned long long)Gg) atomicOr(&g_b32, 1);
    }
}

__device__ __forceinline__ void load_edge(const void* ei, int i, int& src, int& dst) {
    if (i < Ee) {
        if (g_ei32) {
            const int* p = (const int*)ei;
            src = p[i]; dst = p[Ee + i];
        } else {
            const long long* p = (const long long*)ei;
            src = (int)p[i]; dst = (int)p[Ee + i];
        }
    } else {
        src = dst = i - Ee;   // self loops
    }
}

__global__ void count_kernel(const void* ei) {
    int i = blockIdx.x * 256 + threadIdx.x;
    if (i >= ETOT) return;
    int src, dst;
    load_edge(ei, i, src, dst);
    atomicAdd(&g_deg[dst], 1);
}

// ============ 3-phase multi-block exclusive scan ============
__global__ void scanA_kernel() {
    __shared__ int warp_sums[32];
    int tid = threadIdx.x, lane = tid & 31, wid = tid >> 5;
    int i = blockIdx.x * 1024 + tid;
    int v = (i < Nn) ? g_deg[i] : 0;
    int x = v;
#pragma unroll
    for (int off = 1; off < 32; off <<= 1) {
        int y = __shfl_up_sync(0xffffffffu, x, off);
        if (lane >= off) x += y;
    }
    if (lane == 31) warp_sums[wid] = x;
    __syncthreads();
    if (wid == 0) {
        int w = warp_sums[lane];
#pragma unroll
        for (int off = 1; off < 32; off <<= 1) {
            int y = __shfl_up_sync(0xffffffffu, w, off);
            if (lane >= off) w += y;
        }
        warp_sums[lane] = w;
    }
    __syncthreads();
    int woff = wid ? warp_sums[wid - 1] : 0;
    if (i < Nn) g_rowptr[i] = woff + x - v;
    if (tid == 0) g_bsum[blockIdx.x] = warp_sums[31];
}

__global__ void scanB_kernel() {
    __shared__ int ws[4];
    int tid = threadIdx.x, lane = tid & 31, wid = tid >> 5;
    int v = (tid < NB) ? g_bsum[tid] : 0;
    int x = v;
#pragma unroll
    for (int off = 1; off < 32; off <<= 1) {
        int y = __shfl_up_sync(0xffffffffu, x, off);
        if (lane >= off) x += y;
    }
    if (lane == 31) ws[wid] = x;
    __syncthreads();
    int woff = 0;
    for (int k = 0; k < wid; k++) woff += ws[k];
    if (tid < NB) g_boff[tid] = woff + x - v;
    if (tid == 0) g_rowptr[Nn] = ETOT;
}

__global__ void scanC_kernel(const void* batch) {
    int i = blockIdx.x * 1024 + threadIdx.x;
    if (i >= Nn) return;
    int r = g_rowptr[i] + g_boff[blockIdx.x];
    g_rowptr[i] = r;
    g_cursor[i] = r;
    g_batch[i] = g_b32 ? ((const int*)batch)[i] : (int)((const long long*)batch)[i];
}

__global__ void scatter_kernel(const void* ei) {
    int i = blockIdx.x * 256 + threadIdx.x;
    if (i >= ETOT) return;
    int src, dst;
    load_edge(ei, i, src, dst);
    int pos = atomicAdd(&g_cursor[dst], 1);
    g_csrc[pos] = src;
}

// ==== GEMM: 64 nodes/block, f32x2 packed FMA, 4 nodes x 4 cols per thread ===
template <int F, bool TRANS>
__global__ void gemm_kernel(const float* __restrict__ xin,
                            const float* __restrict__ W,
                            const float* __restrict__ a_s,
                            const float* __restrict__ a_d,
                            const float* __restrict__ bprev) {
    __shared__ __align__(16) float Ws[F * Hh];
    __shared__ float xs[64][F + 1];
    __shared__ float as_s[Hh], ad_s[Hh], bs[Hh];

    int tid = threadIdx.x;                 // 256 threads
    for (int i = tid; i < F * Hh; i += 256) Ws[i] = W[i];
    if (tid < Hh) {
        as_s[tid] = a_s[tid];
        ad_s[tid] = a_d[tid];
        if (TRANS) bs[tid] = bprev[tid];
    }
    __syncthreads();   // bs/Ws visible before staging reads them

    int n0 = blockIdx.x * 64;
    for (int i = tid; i < 64 * F; i += 256) {
        int node = i / F, col = i % F;
        float v = 0.f;
        if (n0 + node < Nn) {
            if (TRANS) {
                v = g_agg[(size_t)(n0 + node) * Hh + col] + bs[col];
                v = v > 0.f ? v : (expf(v) - 1.f);   // ELU
            } else {
                v = xin[(n0 + node) * F + col];
            }
        }
        xs[node][col] = v;
    }
    __syncthreads();

    int jj = (tid & 15) * 4;               // 4 output cols
    int nn = (tid >> 4) * 4;               // 4 nodes
    ull acc2[4][2] = {{0, 0}, {0, 0}, {0, 0}, {0, 0}};
#pragma unroll 16
    for (int k = 0; k < F; k++) {
        float4 w = *reinterpret_cast<const float4*>(&Ws[k * Hh + jj]);
        ull w01 = pk2(w.x, w.y);
        ull w23 = pk2(w.z, w.w);
#pragma unroll
        for (int q = 0; q < 4; q++) {
            ull xv = dup2(xs[nn + q][k]);
            ffma2(acc2[q][0], xv, w01);
            ffma2(acc2[q][1], xv, w23);
        }
    }

    float a[4][4];
#pragma unroll
    for (int q = 0; q < 4; q++) {
        float2 f0 = unpk(acc2[q][0]);
        float2 f1 = unpk(acc2[q][1]);
        a[q][0] = f0.x; a[q][1] = f0.y; a[q][2] = f1.x; a[q][3] = f1.y;
    }

    // store h as fp16 (8B per node per thread)
#pragma unroll
    for (int q = 0; q < 4; q++) {
        int n = n0 + nn + q;
        if (n < Nn) {
            __half2* hp = reinterpret_cast<__half2*>(g_hh + (size_t)n * Hh + jj);
            hp[0] = __floats2half2_rn(a[q][0], a[q][1]);
            hp[1] = __floats2half2_rn(a[q][2], a[q][3]);
        }
    }

    // ls/ld: reduce over 16 threads (same nn) via 16-lane shfl subgroups
    float s0 = as_s[jj], s1 = as_s[jj + 1], s2 = as_s[jj + 2], s3 = as_s[jj + 3];
    float d0 = ad_s[jj], d1 = ad_s[jj + 1], d2 = ad_s[jj + 2], d3 = ad_s[jj + 3];
#pragma unroll
    for (int q = 0; q < 4; q++) {
        float rs = a[q][0] * s0 + a[q][1] * s1 + a[q][2] * s2 + a[q][3] * s3;
        float rd = a[q][0] * d0 + a[q][1] * d1 + a[q][2] * d2 + a[q][3] * d3;
#pragma unroll
        for (int off = 1; off < 16; off <<= 1) {
            rs += __shfl_xor_sync(0xffffffffu, rs, off);
            rd += __shfl_xor_sync(0xffffffffu, rd, off);
        }
        if ((tid & 15) == 0) {
            int n = n0 + nn + q;
            if (n < Nn) { g_ls[n] = rs; g_ld[n] = rd; }
        }
    }
}

// == aggregation: warp/dst; smem-cached (src, ex); 4 edges in flight ==
__global__ void agg_kernel() {
    __shared__ float se[8][CAP];
    __shared__ int   ss[8][CAP];
    int gwarp = (blockIdx.x * 256 + threadIdx.x) >> 5;
    int lane  = threadIdx.x & 31;
    int wl    = threadIdx.x >> 5;
    if (gwarp >= Nn) return;
    int dst = gwarp;
    int r0 = g_rowptr[dst], r1 = g_rowptr[dst + 1];
    int d  = r1 - r0;
    float ldv = g_ld[dst];

    // pass 1: load src, compute logits, cache (src, e), running max
    float m = -INFINITY;
    for (int k = lane; k < d; k += 32) {
        int src = g_csrc[r0 + k];
        float e = g_ls[src] + ldv;
        e = e > 0.f ? e : 0.2f * e;
        if (k < CAP) { se[wl][k] = e; ss[wl][k] = src; }
        m = fmaxf(m, e);
    }
#pragma unroll
    for (int off = 16; off; off >>= 1)
        m = fmaxf(m, __shfl_xor_sync(0xffffffffu, m, off));

    // pass 1.5: ex = exp(e - m) in place; den reduction
    float den = 0.f;
    for (int k = lane; k < d; k += 32) {
        float e;
        if (k < CAP) e = se[wl][k];
        else {
            int src = g_csrc[r0 + k];
            e = g_ls[src] + ldv; e = e > 0.f ? e : 0.2f * e;
        }
        float ex = __expf(e - m);
        if (k < CAP) se[wl][k] = ex;
        den += ex;
    }
#pragma unroll
    for (int off = 16; off; off >>= 1)
        den += __shfl_xor_sync(0xffffffffu, den, off);
    __syncwarp();

    // pass 2: 4 subgroups of 8 lanes, one edge each; lane loads 16B (8 halves)
    int sub = lane >> 3;
    int l8  = lane & 7;
    float acc[8] = {0.f, 0.f, 0.f, 0.f, 0.f, 0.f, 0.f, 0.f};
    for (int kk = sub; kk < d; kk += 4) {
        int src; float ex;
        if (kk < CAP) { src = ss[wl][kk]; ex = se[wl][kk]; }
        else {
            src = g_csrc[r0 + kk];
            float e = g_ls[src] + ldv; e = e > 0.f ? e : 0.2f * e;
            ex = __expf(e - m);
        }
        float4 raw = *reinterpret_cast<const float4*>(g_hh + (size_t)src * Hh + l8 * 8);
        const __half2* h2 = reinterpret_cast<const __half2*>(&raw);
#pragma unroll
        for (int t = 0; t < 4; t++) {
            float2 f = __half22float2(h2[t]);
            acc[2 * t]     += ex * f.x;
            acc[2 * t + 1] += ex * f.y;
        }
    }
#pragma unroll
    for (int t = 0; t < 8; t++) {
        acc[t] += __shfl_xor_sync(0xffffffffu, acc[t], 8);
        acc[t] += __shfl_xor_sync(0xffffffffu, acc[t], 16);
    }
    if (sub == 0) {
        float inv = 1.f / den;
        float4 o0 = make_float4(acc[0] * inv, acc[1] * inv, acc[2] * inv, acc[3] * inv);
        float4 o1 = make_float4(acc[4] * inv, acc[5] * inv, acc[6] * inv, acc[7] * inv);
        float4* op = reinterpret_cast<float4*>(g_agg + (size_t)dst * Hh + l8 * 8);
        op[0] = o0; op[1] = o1;
    }
}

// ================= pooling: sorted batch -> contiguous ranges ============
__device__ __forceinline__ int lower_bound_batch(int key) {
    int lo = 0, hi = Nn;
    while (lo < hi) {
        int mid = (lo + hi) >> 1;
        if (g_batch[mid] < key) lo = mid + 1; else hi = mid;
    }
    return lo;
}

__global__ void pool_kernel(const float* __restrict__ b4) {
    __shared__ int s_lo, s_hi;
    __shared__ float red[4][Hh];
    int g = blockIdx.x;
    int tid = threadIdx.x;          // 256 threads
    int j = tid & 63, c = tid >> 6;
    if (tid == 0) s_lo = lower_bound_batch(g);
    if (tid == 1) s_hi = lower_bound_batch(g + 1);
    __syncthreads();
    float bj = b4[j];
    float mx = -INFINITY;
    for (int n = s_lo + c; n < s_hi; n += 4) {
        float v = g_agg[(size_t)n * Hh + j] + bj;
        v = v > 0.f ? v : (expf(v) - 1.f);
        mx = fmaxf(mx, v);
    }
    red[c][j] = mx;
    __syncthreads();
    if (c == 0) {
        mx = fmaxf(fmaxf(red[0][j], red[1][j]), fmaxf(red[2][j], red[3][j]));
        g_pool[g * Hh + j] = mx;
    }
}

// ================= final linear =================
__global__ void final_kernel(const float* __restrict__ lw,
                             const float* __restrict__ lb,
                             float* __restrict__ out) {
    int g = blockIdx.x, j = threadIdx.x;   // 64 threads
    float p = g_pool[g * Hh + j];
    if (!isfinite(p)) p = 0.f;
    float c0 = p * lw[j * 2 + 0];
    float c1 = p * lw[j * 2 + 1];
#pragma unroll
    for (int off = 16; off; off >>= 1) {
        c0 += __shfl_down_sync(0xffffffffu, c0, off);
        c1 += __shfl_down_sync(0xffffffffu, c1, off);
    }
    __shared__ float s[2][2];
    if ((j & 31) == 0) { s[j >> 5][0] = c0; s[j >> 5][1] = c1; }
    __syncthreads();
    if (j == 0) {
        out[2 * g + 0] = s[0][0] + s[1][0] + lb[0];
        out[2 * g + 1] = s[0][1] + s[1][1] + lb[1];
    }
}

// ================= launch =================
extern "C" void kernel_launch(void* const* d_in, const int* in_sizes, int n_in,
                              void* d_out, int out_size) {
    const float* x     = (const float*)d_in[0];
    const void*  ei    = d_in[1];
    const void*  batch = d_in[2];
    const float *W[5], *as[5], *ad[5], *b[5];
    for (int l = 0; l < 5; l++) {
        W[l]  = (const float*)d_in[3 + 4 * l];
        as[l] = (const float*)d_in[4 + 4 * l];
        ad[l] = (const float*)d_in[5 + 4 * l];
        b[l]  = (const float*)d_in[6 + 4 * l];
    }
    const float* lw = (const float*)d_in[23];
    const float* lb = (const float*)d_in[24];
    float* out = (float*)d_out;

    zeroprobe_kernel<<<392, 256>>>(ei, batch);
    count_kernel<<<(ETOT + 255) / 256, 256>>>(ei);
    scanA_kernel<<<NB, 1024>>>();
    scanB_kernel<<<1, 128>>>();
    scanC_kernel<<<NB, 1024>>>(batch);
    scatter_kernel<<<(ETOT + 255) / 256, 256>>>(ei);

    int gemm_grid = (Nn + 63) / 64;
    for (int l = 0; l < 5; l++) {
        if (l == 0)
            gemm_kernel<14, false><<<gemm_grid, 256>>>(x, W[0], as[0], ad[0], nullptr);
        else
            gemm_kernel<64, true><<<gemm_grid, 256>>>(nullptr, W[l], as[l], ad[l], b[l - 1]);
        agg_kernel<<<(Nn * 32 + 255) / 256, 256>>>();
    }
    pool_kernel<<<Gg, 256>>>(b[4]);
    final_kernel<<<Gg, 64>>>(lw, lb, out);
}